// round 12
// baseline (speedup 1.0000x reference)
#include <cuda_runtime.h>
#include <cstdint>
#include <cstddef>

#define NN 100000
#define EE 1600000

// ---------------- scratch (static __device__ arrays; no allocation) ----------------
__device__ float g_P[(size_t)NN * 256];    // projected neighbor features (layer1: 256 cols, layer2: 128)
__device__ float g_Q[(size_t)NN * 256];    // projected self features
__device__ float g_H[(size_t)NN * 256];    // hidden h1 [N,256]; later reused: p3 = g_H[0..N), q3 = g_H[N..2N)
__device__ float g_Wcat[256 * 512];        // concatenated [K, 2h] weights (pre-rounded to tf32)
__device__ int   g_rowptr[NN + 1];
__device__ int   g_cursor[NN];
__device__ int   g_cnt[NN];
__device__ int   g_adj[EE];
__device__ int   g_part[128];
__device__ int   g_is64;                   // 1 if edge_index is int64, 0 if int32

// ---------------- small helpers ----------------
__device__ __forceinline__ float4 f4add(float4 a, float4 b) {
    return make_float4(a.x + b.x, a.y + b.y, a.z + b.z, a.w + b.w);
}
__device__ __forceinline__ float4 f4scale(float4 a, float s) {
    return make_float4(a.x * s, a.y * s, a.z * s, a.w * s);
}
__device__ __forceinline__ float4 f4relu(float4 a) {
    return make_float4(fmaxf(a.x, 0.f), fmaxf(a.y, 0.f), fmaxf(a.z, 0.f), fmaxf(a.w, 0.f));
}
__device__ __forceinline__ uint32_t f2tf(float f) {
    uint32_t r;
    asm("cvt.rna.tf32.f32 %0, %1;" : "=r"(r) : "f"(f));
    return r;
}
__device__ __forceinline__ void mma_tf32(float* d, const uint32_t* a, const uint32_t* b) {
    asm("mma.sync.aligned.m16n8k8.row.col.f32.tf32.tf32.f32 "
        "{%0,%1,%2,%3}, {%4,%5,%6,%7}, {%8,%9}, {%0,%1,%2,%3};"
        : "+f"(d[0]), "+f"(d[1]), "+f"(d[2]), "+f"(d[3])
        : "r"(a[0]), "r"(a[1]), "r"(a[2]), "r"(a[3]), "r"(b[0]), "r"(b[1]));
}
__device__ __forceinline__ void cpasync16(void* smem, const void* g, int src_sz) {
    uint32_t s = (uint32_t)__cvta_generic_to_shared(smem);
    asm volatile("cp.async.cg.shared.global [%0], [%1], 16, %2;" ::"r"(s), "l"(g), "r"(src_sz));
}
__device__ __forceinline__ int clampi(int v) {
    return v < 0 ? 0 : (v >= NN ? NN - 1 : v);
}
// dtype-agnostic index loads (position p in the flat [2, EE] array)
__device__ __forceinline__ int load_idx(const void* ei, int p) {
    if (g_is64) return clampi((int)((const long long*)ei)[p]);
    return clampi(((const int*)ei)[p]);
}
__device__ __forceinline__ float4 ldcs4(const float4* p) {
    return __ldcs(p);
}

// ---------------- dtype detection: int64 values < 2^31 have zero high words ----------------
__global__ void k_detect(const int* __restrict__ ei32) {
    int t = threadIdx.x;
    int v = ei32[2 * t + 1];  // reads within first 8KB: safe for both dtypes
    int all0 = __syncthreads_and(v == 0);
    if (t == 0) g_is64 = all0;
}

// ---------------- CSR build ----------------
__global__ void k_zero_cnt() {
    int i = blockIdx.x * blockDim.x + threadIdx.x;
    if (i < NN) g_cnt[i] = 0;
}
__global__ void k_hist(const void* __restrict__ ei) {
    int e = blockIdx.x * blockDim.x + threadIdx.x;
    if (e < EE) atomicAdd(&g_cnt[load_idx(ei, EE + e)], 1);
}
// blocks of 1024: local exclusive scan -> g_rowptr, block sums -> g_part
__global__ void k_scan1() {
    __shared__ int wsum[32];
    int t = threadIdx.x;
    int i = blockIdx.x * 1024 + t;
    int v = (i < NN) ? g_cnt[i] : 0;
    int incl = v;
#pragma unroll
    for (int o = 1; o < 32; o <<= 1) {
        int n = __shfl_up_sync(0xffffffffu, incl, o);
        if ((t & 31) >= o) incl += n;
    }
    if ((t & 31) == 31) wsum[t >> 5] = incl;
    __syncthreads();
    if (t < 32) {
        int w = wsum[t];
        int wi = w;
#pragma unroll
        for (int o = 1; o < 32; o <<= 1) {
            int n = __shfl_up_sync(0xffffffffu, wi, o);
            if (t >= o) wi += n;
        }
        wsum[t] = wi - w;  // exclusive warp offset
        if (t == 31) g_part[blockIdx.x] = wi;  // block total
    }
    __syncthreads();
    if (i < NN) g_rowptr[i] = incl - v + wsum[t >> 5];
}
__global__ void k_scan2(int nb) {
    int acc = 0;
    for (int b = 0; b < nb; b++) {
        int s = g_part[b];
        g_part[b] = acc;
        acc += s;
    }
    g_rowptr[NN] = acc;
}
__global__ void k_scan3() {
    int i = blockIdx.x * 1024 + threadIdx.x;
    if (i < NN) {
        int r = g_rowptr[i] + g_part[blockIdx.x];
        g_rowptr[i] = r;
        g_cursor[i] = r;
    }
}
__global__ void k_fill(const void* __restrict__ ei) {
    int e = blockIdx.x * blockDim.x + threadIdx.x;
    if (e < EE) {
        int dst = load_idx(ei, EE + e);
        int pos = atomicAdd(&g_cursor[dst], 1);
        g_adj[pos] = load_idx(ei, e);
    }
}

// ---------------- weight concat (pre-rounded to tf32): g_Wcat[k][c] ----------------
__global__ void k_concat(const float* __restrict__ Wl, const float* __restrict__ Wr, int K, int h) {
    int i = blockIdx.x * blockDim.x + threadIdx.x;
    int tot = K * 2 * h;
    if (i < tot) {
        int k = i / (2 * h);
        int c = i % (2 * h);
        float v = (c < h) ? Wl[k * h + c] : Wr[k * h + c - h];
        g_Wcat[i] = __uint_as_float(f2tf(v));  // round-to-nearest tf32, stored as fp32 bits
    }
}

// ---------------- tf32 GEMM: [P|Q][M, Nh each] = A[M,K] @ g_Wcat[K,N],  N = 2*Nh ----------------
// A = Aext if non-null, else g_H. Output split: cols [0,Nh) -> g_P, [Nh,N) -> g_Q (row stride Nh).
// Block tile 128x64, k-tile 32, 8 warps in 4x2 grid (warp tile 32x32). 3 CTAs/SM for occupancy.
// grid: (x = N/64 tiles, y = M/128 tiles) so consecutive blocks share A rows -> single DRAM pass.
#define AS_ST 36   // As[m][k], stride 36 floats
#define BS_ST 72   // Bs[k][n], 64 cols + 8 pad

__device__ __forceinline__ void gemm_load_tile(const float* __restrict__ A, float* As, float* Bs,
                                               int bm, int bn, int M, int K, int N, int k0,
                                               int a_r, int a_kq, int b_r, int b_c) {
    const float* B = g_Wcat;
#pragma unroll
    for (int it = 0; it < 4; it++) {
        int r = a_r + 32 * it;
        int gr = bm + r;
        bool val = gr < M;
        const float* src = A + (size_t)(val ? gr : 0) * K + k0 + 4 * a_kq;
        cpasync16(&As[r * AS_ST + 4 * a_kq], src, val ? 16 : 0);
    }
#pragma unroll
    for (int it = 0; it < 2; it++) {
        int kk = b_r + 16 * it;
        cpasync16(&Bs[kk * BS_ST + 4 * b_c], B + (size_t)(k0 + kk) * N + bn + 4 * b_c, 16);
    }
    asm volatile("cp.async.commit_group;");
}

__global__ void __launch_bounds__(256, 3) k_gemm(const float* __restrict__ Aext, int M, int K,
                                                 int N) {
    extern __shared__ float smem[];
    float* As0 = smem;                      // 128*36
    float* As1 = smem + 128 * AS_ST;
    float* Bs0 = smem + 2 * 128 * AS_ST;    // 32*72
    float* Bs1 = Bs0 + 32 * BS_ST;
    const float* A = Aext ? Aext : g_H;

    int tid = threadIdx.x;
    int bm = blockIdx.y * 128, bn = blockIdx.x * 64;   // y = rows, x = cols
    int warp = tid >> 5, lane = tid & 31;
    int wm = (warp >> 1) * 32, wn = (warp & 1) * 32;   // 4x2 warp grid, 32x32 tiles
    int grp = lane >> 2, qid = lane & 3;
    int a_r = tid >> 3, a_kq = tid & 7;                // A: 32 rows/iter x 8 chunks
    int b_r = tid >> 4, b_c = tid & 15;                // B: 16 rows/iter x 16 chunks

    // output split
    int Nh = N >> 1;
    float* Cb = (bn < Nh) ? g_P : g_Q;
    int bncol = (bn < Nh) ? bn : bn - Nh;

    float acc[2][4][4];
#pragma unroll
    for (int i = 0; i < 2; i++)
#pragma unroll
        for (int j = 0; j < 4; j++)
#pragma unroll
            for (int r = 0; r < 4; r++) acc[i][j][r] = 0.f;

    int ktiles = K / 32;
    gemm_load_tile(A, As0, Bs0, bm, bn, M, K, N, 0, a_r, a_kq, b_r, b_c);

    for (int kt = 0; kt < ktiles; kt++) {
        if (kt + 1 < ktiles) {
            float* Asn = ((kt + 1) & 1) ? As1 : As0;
            float* Bsn = ((kt + 1) & 1) ? Bs1 : Bs0;
            gemm_load_tile(A, Asn, Bsn, bm, bn, M, K, N, (kt + 1) * 32, a_r, a_kq, b_r, b_c);
            asm volatile("cp.async.wait_group 1;");
        } else {
            asm volatile("cp.async.wait_group 0;");
        }
        __syncthreads();

        const float* Asb = (kt & 1) ? As1 : As0;
        const float* Bsb = (kt & 1) ? Bs1 : Bs0;
#pragma unroll
        for (int ks = 0; ks < 4; ks++) {
            int k0 = ks * 8;
            uint32_t af[2][4];
#pragma unroll
            for (int mf = 0; mf < 2; mf++) {
                const float* ap = &Asb[(wm + mf * 16 + grp) * AS_ST + k0 + qid];
                af[mf][0] = f2tf(ap[0]);
                af[mf][1] = f2tf(ap[8 * AS_ST]);
                af[mf][2] = f2tf(ap[4]);
                af[mf][3] = f2tf(ap[8 * AS_ST + 4]);
            }
            uint32_t bf[4][2];
#pragma unroll
            for (int nf = 0; nf < 4; nf++) {
                const uint32_t* bp =
                    (const uint32_t*)&Bsb[(k0 + qid) * BS_ST + wn + nf * 8 + grp];
                bf[nf][0] = bp[0];             // B pre-rounded to tf32 in k_concat
                bf[nf][1] = bp[4 * BS_ST];
            }
#pragma unroll
            for (int mf = 0; mf < 2; mf++)
#pragma unroll
                for (int nf = 0; nf < 4; nf++) mma_tf32(acc[mf][nf], af[mf], bf[nf]);
        }
        __syncthreads();
    }

    // epilogue
#pragma unroll
    for (int mf = 0; mf < 2; mf++) {
        int r0 = bm + wm + mf * 16 + grp;
#pragma unroll
        for (int nf = 0; nf < 4; nf++) {
            int col = bncol + wn + nf * 8 + qid * 2;
            if (r0 < M)
                *(float2*)&Cb[(size_t)r0 * Nh + col] = make_float2(acc[mf][nf][0], acc[mf][nf][1]);
            if (r0 + 8 < M)
                *(float2*)&Cb[(size_t)(r0 + 8) * Nh + col] =
                    make_float2(acc[mf][nf][2], acc[mf][nf][3]);
        }
    }
}

// ---------------- aggregation: g_H[i] = relu( mean_nbr(P) + b + Q[i] ), warp per node ----------------
template <int D>
__global__ void k_agg(const float* __restrict__ bias) {
    int node = (int)((blockIdx.x * (unsigned)blockDim.x + threadIdx.x) >> 5);
    if (node >= NN) return;
    const float* P = g_P;
    int lane = threadIdx.x & 31;
    int s = g_rowptr[node], e = g_rowptr[node + 1];
    float4 a0 = make_float4(0, 0, 0, 0), a1 = make_float4(0, 0, 0, 0);
    int i = s;
    for (; i + 4 <= e; i += 4) {
        const float4* r0 = (const float4*)(P + (size_t)g_adj[i] * D);
        const float4* r1 = (const float4*)(P + (size_t)g_adj[i + 1] * D);
        const float4* r2 = (const float4*)(P + (size_t)g_adj[i + 2] * D);
        const float4* r3 = (const float4*)(P + (size_t)g_adj[i + 3] * D);
        float4 x0 = r0[lane], x1 = r1[lane], x2 = r2[lane], x3 = r3[lane];
        a0 = f4add(a0, f4add(f4add(x0, x1), f4add(x2, x3)));
        if (D == 256) {
            float4 y0 = r0[lane + 32], y1 = r1[lane + 32], y2 = r2[lane + 32],
                   y3 = r3[lane + 32];
            a1 = f4add(a1, f4add(f4add(y0, y1), f4add(y2, y3)));
        }
    }
    for (; i < e; i++) {
        const float4* r0 = (const float4*)(P + (size_t)g_adj[i] * D);
        a0 = f4add(a0, r0[lane]);
        if (D == 256) a1 = f4add(a1, r0[lane + 32]);
    }
    int deg = e - s;
    float inv = 1.0f / (float)(deg > 1 ? deg : 1);
    const float4* self = (const float4*)(g_Q + (size_t)node * D);
    const float4* bb = (const float4*)bias;
    float4* op = (float4*)(g_H + (size_t)node * D);
    __stcs(&op[lane], f4relu(f4add(f4add(f4scale(a0, inv), bb[lane]), ldcs4(&self[lane]))));
    if (D == 256)
        __stcs(&op[lane + 32],
               f4relu(f4add(f4add(f4scale(a1, inv), bb[lane + 32]), ldcs4(&self[lane + 32]))));
}

// layer-2 aggregation fused with layer-3 projection: writes p3 (g_H[0..N)) and q3 (g_H[N..2N))
__global__ void k_agg2_fuse(const float* __restrict__ b2, const float* __restrict__ Wl3,
                            const float* __restrict__ Wr3) {
    int node = (int)((blockIdx.x * (unsigned)blockDim.x + threadIdx.x) >> 5);
    if (node >= NN) return;
    const float* P = g_P;
    int lane = threadIdx.x & 31;
    int s = g_rowptr[node], e = g_rowptr[node + 1];
    float4 a0 = make_float4(0, 0, 0, 0);
    int i = s;
    for (; i + 4 <= e; i += 4) {
        const float4* r0 = (const float4*)(P + (size_t)g_adj[i] * 128);
        const float4* r1 = (const float4*)(P + (size_t)g_adj[i + 1] * 128);
        const float4* r2 = (const float4*)(P + (size_t)g_adj[i + 2] * 128);
        const float4* r3 = (const float4*)(P + (size_t)g_adj[i + 3] * 128);
        a0 = f4add(a0, f4add(f4add(r0[lane], r1[lane]), f4add(r2[lane], r3[lane])));
    }
    for (; i < e; i++) {
        const float4* r0 = (const float4*)(P + (size_t)g_adj[i] * 128);
        a0 = f4add(a0, r0[lane]);
    }
    int deg = e - s;
    float inv = 1.0f / (float)(deg > 1 ? deg : 1);
    const float4 sf = ldcs4(&((const float4*)(g_Q + (size_t)node * 128))[lane]);
    const float4 bb = ((const float4*)b2)[lane];
    float4 h = f4relu(f4add(f4add(f4scale(a0, inv), bb), sf));
    float4 wl = ((const float4*)Wl3)[lane];
    float4 wr = ((const float4*)Wr3)[lane];
    float pl = h.x * wl.x + h.y * wl.y + h.z * wl.z + h.w * wl.w;
    float pr = h.x * wr.x + h.y * wr.y + h.z * wr.z + h.w * wr.w;
#pragma unroll
    for (int o = 16; o > 0; o >>= 1) {
        pl += __shfl_down_sync(0xffffffffu, pl, o);
        pr += __shfl_down_sync(0xffffffffu, pr, o);
    }
    if (lane == 0) {
        g_H[node] = pl;
        g_H[NN + node] = pr;
    }
}

__global__ void k_final(const float* __restrict__ b3, float* __restrict__ out) {
    int i = blockIdx.x * blockDim.x + threadIdx.x;
    if (i >= NN) return;
    int s = g_rowptr[i], e = g_rowptr[i + 1];
    float sum = 0.f;
    for (int k = s; k < e; k++) sum += g_H[g_adj[k]];
    int deg = e - s;
    out[i] = sum / (float)(deg > 1 ? deg : 1) + b3[0] + g_H[NN + i];
}

// ---------------- launch ----------------
extern "C" void kernel_launch(void* const* d_in, const int* in_sizes, int n_in, void* d_out,
                              int out_size) {
    const float* x = (const float*)d_in[0];
    const void* ei = d_in[1];
    const float* Wl1 = (const float*)d_in[2];
    const float* bl1 = (const float*)d_in[3];
    const float* Wr1 = (const float*)d_in[4];
    const float* Wl2 = (const float*)d_in[5];
    const float* bl2 = (const float*)d_in[6];
    const float* Wr2 = (const float*)d_in[7];
    const float* Wl3 = (const float*)d_in[8];
    const float* bl3 = (const float*)d_in[9];
    const float* Wr3 = (const float*)d_in[10];
    float* out = (float*)d_out;

    const int SMEM = (2 * 128 * AS_ST + 2 * 32 * BS_ST) * 4;  // 55296 bytes
    static bool attr_set = false;
    if (!attr_set) {
        cudaFuncSetAttribute(k_gemm, cudaFuncAttributeMaxDynamicSharedMemorySize, SMEM);
        attr_set = true;
    }

    int scan_blocks = (NN + 1023) / 1024;  // 98

    // Launch order keeps k_gemm (layer 1) in the ncu capture window (4th launch).
    k_concat<<<(256 * 512 + 255) / 256, 256>>>(Wl1, Wr1, 256, 256);  // 0
    k_detect<<<1, 1024>>>((const int*)ei);                            // 1
    k_zero_cnt<<<(NN + 255) / 256, 256>>>();                          // 2
    dim3 g1(8, (NN + 127) / 128);                                     // x=bn tiles(64), y=rows
    k_gemm<<<g1, 256, SMEM>>>(x, NN, 256, 512);                       // 3 <- profiled
    k_hist<<<(EE + 255) / 256, 256>>>(ei);
    k_scan1<<<scan_blocks, 1024>>>();
    k_scan2<<<1, 1>>>(scan_blocks);
    k_scan3<<<scan_blocks, 1024>>>();
    k_fill<<<(EE + 255) / 256, 256>>>(ei);

    // layer 1 aggregation -> H [N,256]
    k_agg<256><<<((size_t)NN * 32 + 255) / 256, 256>>>(bl1);

    // layer 2: P2|Q2 = H @ [Wl2|Wr2] (N=256), then agg+relu fused with layer-3 projection
    k_concat<<<(256 * 256 + 255) / 256, 256>>>(Wl2, Wr2, 256, 128);
    dim3 g2(4, (NN + 127) / 128);
    k_gemm<<<g2, 256, SMEM>>>(nullptr, NN, 256, 256);
    k_agg2_fuse<<<((size_t)NN * 32 + 255) / 256, 256>>>(bl2, Wl3, Wr3);

    // layer 3: scalar aggregation
    k_final<<<(NN + 255) / 256, 256>>>(bl3, out);
}

// round 15
// speedup vs baseline: 1.2832x; 1.2832x over previous
#include <cuda_runtime.h>
#include <cuda_bf16.h>
#include <cstdint>
#include <cstddef>

#define NN 100000
#define EE 1600000

// ---------------- scratch (static __device__ arrays; no allocation) ----------------
__device__ __nv_bfloat16 g_Pb[(size_t)NN * 256];  // projected neighbor features, bf16
__device__ float g_Q[(size_t)NN * 256];    // projected self features, fp32
__device__ float g_H[(size_t)NN * 256];    // hidden h1 [N,256]; later: p3 = g_H[0..N), q3 = g_H[N..2N)
__device__ float g_Wcat[256 * 512];        // concatenated [K, 2h] weights (pre-rounded to tf32)
__device__ int   g_rowptr[NN + 1];
__device__ int   g_cursor[NN];
__device__ int   g_cnt[NN];
__device__ int   g_adj[EE];
__device__ int   g_part[128];
__device__ int   g_is64;                   // 1 if edge_index is int64, 0 if int32

// ---------------- small helpers ----------------
__device__ __forceinline__ float4 f4add(float4 a, float4 b) {
    return make_float4(a.x + b.x, a.y + b.y, a.z + b.z, a.w + b.w);
}
__device__ __forceinline__ float4 f4relu(float4 a) {
    return make_float4(fmaxf(a.x, 0.f), fmaxf(a.y, 0.f), fmaxf(a.z, 0.f), fmaxf(a.w, 0.f));
}
__device__ __forceinline__ uint32_t f2tf(float f) {
    uint32_t r;
    asm("cvt.rna.tf32.f32 %0, %1;" : "=r"(r) : "f"(f));
    return r;
}
__device__ __forceinline__ void mma_tf32(float* d, const uint32_t* a, const uint32_t* b) {
    asm("mma.sync.aligned.m16n8k8.row.col.f32.tf32.tf32.f32 "
        "{%0,%1,%2,%3}, {%4,%5,%6,%7}, {%8,%9}, {%0,%1,%2,%3};"
        : "+f"(d[0]), "+f"(d[1]), "+f"(d[2]), "+f"(d[3])
        : "r"(a[0]), "r"(a[1]), "r"(a[2]), "r"(a[3]), "r"(b[0]), "r"(b[1]));
}
__device__ __forceinline__ void cpasync16(void* smem, const void* g, int src_sz) {
    uint32_t s = (uint32_t)__cvta_generic_to_shared(smem);
    asm volatile("cp.async.cg.shared.global [%0], [%1], 16, %2;" ::"r"(s), "l"(g), "r"(src_sz));
}
__device__ __forceinline__ int clampi(int v) {
    return v < 0 ? 0 : (v >= NN ? NN - 1 : v);
}
__device__ __forceinline__ int load_idx(const void* ei, int p) {
    if (g_is64) return clampi((int)((const long long*)ei)[p]);
    return clampi(((const int*)ei)[p]);
}
// accumulate 8 bf16 (one uint4) into 8 fp32 accs
__device__ __forceinline__ void acc8(float* a, uint4 u) {
    float2 f0 = __bfloat1622float2(*(const __nv_bfloat162*)&u.x);
    float2 f1 = __bfloat1622float2(*(const __nv_bfloat162*)&u.y);
    float2 f2 = __bfloat1622float2(*(const __nv_bfloat162*)&u.z);
    float2 f3 = __bfloat1622float2(*(const __nv_bfloat162*)&u.w);
    a[0] += f0.x; a[1] += f0.y; a[2] += f1.x; a[3] += f1.y;
    a[4] += f2.x; a[5] += f2.y; a[6] += f3.x; a[7] += f3.y;
}
__device__ __forceinline__ void acc4(float* a, uint2 u) {
    float2 f0 = __bfloat1622float2(*(const __nv_bfloat162*)&u.x);
    float2 f1 = __bfloat1622float2(*(const __nv_bfloat162*)&u.y);
    a[0] += f0.x; a[1] += f0.y; a[2] += f1.x; a[3] += f1.y;
}

// ---------------- dtype detection ----------------
__global__ void k_detect(const int* __restrict__ ei32) {
    int t = threadIdx.x;
    int v = ei32[2 * t + 1];
    int all0 = __syncthreads_and(v == 0);
    if (t == 0) g_is64 = all0;
}

// ---------------- CSR build ----------------
__global__ void k_zero_cnt() {
    int i = blockIdx.x * blockDim.x + threadIdx.x;
    if (i < NN) g_cnt[i] = 0;
}
__global__ void k_hist(const void* __restrict__ ei) {
    int e = blockIdx.x * blockDim.x + threadIdx.x;
    if (e < EE) atomicAdd(&g_cnt[load_idx(ei, EE + e)], 1);
}
__global__ void k_scan1() {
    __shared__ int wsum[32];
    int t = threadIdx.x;
    int i = blockIdx.x * 1024 + t;
    int v = (i < NN) ? g_cnt[i] : 0;
    int incl = v;
#pragma unroll
    for (int o = 1; o < 32; o <<= 1) {
        int n = __shfl_up_sync(0xffffffffu, incl, o);
        if ((t & 31) >= o) incl += n;
    }
    if ((t & 31) == 31) wsum[t >> 5] = incl;
    __syncthreads();
    if (t < 32) {
        int w = wsum[t];
        int wi = w;
#pragma unroll
        for (int o = 1; o < 32; o <<= 1) {
            int n = __shfl_up_sync(0xffffffffu, wi, o);
            if (t >= o) wi += n;
        }
        wsum[t] = wi - w;
        if (t == 31) g_part[blockIdx.x] = wi;
    }
    __syncthreads();
    if (i < NN) g_rowptr[i] = incl - v + wsum[t >> 5];
}
__global__ void k_scan2(int nb) {
    int acc = 0;
    for (int b = 0; b < nb; b++) {
        int s = g_part[b];
        g_part[b] = acc;
        acc += s;
    }
    g_rowptr[NN] = acc;
}
__global__ void k_scan3() {
    int i = blockIdx.x * 1024 + threadIdx.x;
    if (i < NN) {
        int r = g_rowptr[i] + g_part[blockIdx.x];
        g_rowptr[i] = r;
        g_cursor[i] = r;
    }
}
__global__ void k_fill(const void* __restrict__ ei) {
    int e = blockIdx.x * blockDim.x + threadIdx.x;
    if (e < EE) {
        int dst = load_idx(ei, EE + e);
        int pos = atomicAdd(&g_cursor[dst], 1);
        g_adj[pos] = load_idx(ei, e);
    }
}

// ---------------- weight concat (pre-rounded to tf32) ----------------
__global__ void k_concat(const float* __restrict__ Wl, const float* __restrict__ Wr, int K, int h) {
    int i = blockIdx.x * blockDim.x + threadIdx.x;
    int tot = K * 2 * h;
    if (i < tot) {
        int k = i / (2 * h);
        int c = i % (2 * h);
        float v = (c < h) ? Wl[k * h + c] : Wr[k * h + c - h];
        g_Wcat[i] = __uint_as_float(f2tf(v));
    }
}

// ---------------- tf32 GEMM (R11 shape): block 128x128, warp 64x32, k-tile 32 ----------------
// Output split: cols [0,Nh) -> g_Pb (bf16), [Nh,N) -> g_Q (fp32), row stride Nh.
#define AS_ST 36
#define BS_ST 136

__device__ __forceinline__ void gemm_load_tile(const float* __restrict__ A, float* As, float* Bs,
                                               int bm, int bn, int M, int K, int N, int k0,
                                               int a_r, int a_kq, int b_k, int b_nq) {
    const float* B = g_Wcat;
#pragma unroll
    for (int it = 0; it < 4; it++) {
        int r = a_r + 32 * it;
        int gr = bm + r;
        bool val = gr < M;
        const float* src = A + (size_t)(val ? gr : 0) * K + k0 + 4 * a_kq;
        cpasync16(&As[r * AS_ST + 4 * a_kq], src, val ? 16 : 0);
    }
#pragma unroll
    for (int it = 0; it < 4; it++) {
        int kk = b_k + 8 * it;
        cpasync16(&Bs[kk * BS_ST + 4 * b_nq], B + (size_t)(k0 + kk) * N + bn + 4 * b_nq, 16);
    }
    asm volatile("cp.async.commit_group;");
}

__global__ void __launch_bounds__(256, 2) k_gemm(const float* __restrict__ Aext, int M, int K,
                                                 int N) {
    extern __shared__ float smem[];
    float* As0 = smem;
    float* As1 = smem + 128 * AS_ST;
    float* Bs0 = smem + 2 * 128 * AS_ST;
    float* Bs1 = Bs0 + 32 * BS_ST;
    const float* A = Aext ? Aext : g_H;

    int tid = threadIdx.x;
    int bm = blockIdx.y * 128, bn = blockIdx.x * 128;
    int warp = tid >> 5, lane = tid & 31;
    int wm = (warp >> 2) * 64, wn = (warp & 3) * 32;
    int grp = lane >> 2, qid = lane & 3;
    int a_r = tid >> 3, a_kq = tid & 7;
    int b_k = tid >> 5, b_nq = tid & 31;

    int Nh = N >> 1;
    bool isP = (bn < Nh);
    int bncol = isP ? bn : bn - Nh;

    float acc[4][4][4];
#pragma unroll
    for (int i = 0; i < 4; i++)
#pragma unroll
        for (int j = 0; j < 4; j++)
#pragma unroll
            for (int r = 0; r < 4; r++) acc[i][j][r] = 0.f;

    int ktiles = K / 32;
    gemm_load_tile(A, As0, Bs0, bm, bn, M, K, N, 0, a_r, a_kq, b_k, b_nq);

    for (int kt = 0; kt < ktiles; kt++) {
        if (kt + 1 < ktiles) {
            float* Asn = ((kt + 1) & 1) ? As1 : As0;
            float* Bsn = ((kt + 1) & 1) ? Bs1 : Bs0;
            gemm_load_tile(A, Asn, Bsn, bm, bn, M, K, N, (kt + 1) * 32, a_r, a_kq, b_k, b_nq);
            asm volatile("cp.async.wait_group 1;");
        } else {
            asm volatile("cp.async.wait_group 0;");
        }
        __syncthreads();

        const float* Asb = (kt & 1) ? As1 : As0;
        const uint32_t* Bsb = (const uint32_t*)((kt & 1) ? Bs1 : Bs0);
#pragma unroll
        for (int ks = 0; ks < 4; ks++) {
            int k0 = ks * 8;
            uint32_t af[4][4];
#pragma unroll
            for (int mf = 0; mf < 4; mf++) {
                const float* ap = &Asb[(wm + mf * 16 + grp) * AS_ST + k0 + qid];
                af[mf][0] = f2tf(ap[0]);               // round-to-nearest tf32 on A
                af[mf][1] = f2tf(ap[8 * AS_ST]);
                af[mf][2] = f2tf(ap[4]);
                af[mf][3] = f2tf(ap[8 * AS_ST + 4]);
            }
            uint32_t bf[4][2];
#pragma unroll
            for (int nf = 0; nf < 4; nf++) {
                const uint32_t* bp = &Bsb[(k0 + qid) * BS_ST + wn + nf * 8 + grp];
                bf[nf][0] = bp[0];                     // B pre-rounded in k_concat
                bf[nf][1] = bp[4 * BS_ST];
            }
#pragma unroll
            for (int mf = 0; mf < 4; mf++)
#pragma unroll
                for (int nf = 0; nf < 4; nf++) mma_tf32(acc[mf][nf], af[mf], bf[nf]);
        }
        __syncthreads();
    }

    // epilogue: P half -> bf16, Q half -> fp32
#pragma unroll
    for (int mf = 0; mf < 4; mf++) {
        int r0 = bm + wm + mf * 16 + grp;
#pragma unroll
        for (int nf = 0; nf < 4; nf++) {
            int col = bncol + wn + nf * 8 + qid * 2;
            if (isP) {
                if (r0 < M)
                    *(__nv_bfloat162*)&g_Pb[(size_t)r0 * Nh + col] =
                        __floats2bfloat162_rn(acc[mf][nf][0], acc[mf][nf][1]);
                if (r0 + 8 < M)
                    *(__nv_bfloat162*)&g_Pb[(size_t)(r0 + 8) * Nh + col] =
                        __floats2bfloat162_rn(acc[mf][nf][2], acc[mf][nf][3]);
            } else {
                if (r0 < M)
                    *(float2*)&g_Q[(size_t)r0 * Nh + col] =
                        make_float2(acc[mf][nf][0], acc[mf][nf][1]);
                if (r0 + 8 < M)
                    *(float2*)&g_Q[(size_t)(r0 + 8) * Nh + col] =
                        make_float2(acc[mf][nf][2], acc[mf][nf][3]);
            }
        }
    }
}

// ---------------- layer-1 aggregation: 8-edge unrolled bf16 gather ----------------
__global__ void k_agg(const float* __restrict__ bias) {
    int node = (int)((blockIdx.x * (unsigned)blockDim.x + threadIdx.x) >> 5);
    if (node >= NN) return;
    int lane = threadIdx.x & 31;
    int s = g_rowptr[node], e = g_rowptr[node + 1];
    float a[8] = {0, 0, 0, 0, 0, 0, 0, 0};
    int i = s;
    for (; i + 8 <= e; i += 8) {
        uint4 u0 = ((const uint4*)(g_Pb + (size_t)g_adj[i] * 256))[lane];
        uint4 u1 = ((const uint4*)(g_Pb + (size_t)g_adj[i + 1] * 256))[lane];
        uint4 u2 = ((const uint4*)(g_Pb + (size_t)g_adj[i + 2] * 256))[lane];
        uint4 u3 = ((const uint4*)(g_Pb + (size_t)g_adj[i + 3] * 256))[lane];
        uint4 u4 = ((const uint4*)(g_Pb + (size_t)g_adj[i + 4] * 256))[lane];
        uint4 u5 = ((const uint4*)(g_Pb + (size_t)g_adj[i + 5] * 256))[lane];
        uint4 u6 = ((const uint4*)(g_Pb + (size_t)g_adj[i + 6] * 256))[lane];
        uint4 u7 = ((const uint4*)(g_Pb + (size_t)g_adj[i + 7] * 256))[lane];
        acc8(a, u0); acc8(a, u1); acc8(a, u2); acc8(a, u3);
        acc8(a, u4); acc8(a, u5); acc8(a, u6); acc8(a, u7);
    }
    if (i + 4 <= e) {
        uint4 u0 = ((const uint4*)(g_Pb + (size_t)g_adj[i] * 256))[lane];
        uint4 u1 = ((const uint4*)(g_Pb + (size_t)g_adj[i + 1] * 256))[lane];
        uint4 u2 = ((const uint4*)(g_Pb + (size_t)g_adj[i + 2] * 256))[lane];
        uint4 u3 = ((const uint4*)(g_Pb + (size_t)g_adj[i + 3] * 256))[lane];
        acc8(a, u0); acc8(a, u1); acc8(a, u2); acc8(a, u3);
        i += 4;
    }
    for (; i < e; i++) acc8(a, ((const uint4*)(g_Pb + (size_t)g_adj[i] * 256))[lane]);
    int deg = e - s;
    float inv = 1.0f / (float)(deg > 1 ? deg : 1);
    int c0 = lane * 8;
    const float4* self = (const float4*)(g_Q + (size_t)node * 256 + c0);
    const float4* bb = (const float4*)(bias + c0);
    float4 s0 = __ldcs(&self[0]), s1 = __ldcs(&self[1]);
    float4 b0 = bb[0], b1 = bb[1];
    float4 o0 = f4relu(make_float4(fmaf(a[0], inv, b0.x + s0.x), fmaf(a[1], inv, b0.y + s0.y),
                                   fmaf(a[2], inv, b0.z + s0.z), fmaf(a[3], inv, b0.w + s0.w)));
    float4 o1 = f4relu(make_float4(fmaf(a[4], inv, b1.x + s1.x), fmaf(a[5], inv, b1.y + s1.y),
                                   fmaf(a[6], inv, b1.z + s1.z), fmaf(a[7], inv, b1.w + s1.w)));
    float4* op = (float4*)(g_H + (size_t)node * 256 + c0);
    __stcs(&op[0], o0);
    __stcs(&op[1], o1);
}

// ---------------- layer-2 agg fused with layer-3 projection (8-edge unrolled bf16) ----------------
__global__ void k_agg2_fuse(const float* __restrict__ b2, const float* __restrict__ Wl3,
                            const float* __restrict__ Wr3) {
    int node = (int)((blockIdx.x * (unsigned)blockDim.x + threadIdx.x) >> 5);
    if (node >= NN) return;
    int lane = threadIdx.x & 31;
    int s = g_rowptr[node], e = g_rowptr[node + 1];
    float a[4] = {0, 0, 0, 0};
    int i = s;
    for (; i + 8 <= e; i += 8) {
        uint2 u0 = ((const uint2*)(g_Pb + (size_t)g_adj[i] * 128))[lane];
        uint2 u1 = ((const uint2*)(g_Pb + (size_t)g_adj[i + 1] * 128))[lane];
        uint2 u2 = ((const uint2*)(g_Pb + (size_t)g_adj[i + 2] * 128))[lane];
        uint2 u3 = ((const uint2*)(g_Pb + (size_t)g_adj[i + 3] * 128))[lane];
        uint2 u4 = ((const uint2*)(g_Pb + (size_t)g_adj[i + 4] * 128))[lane];
        uint2 u5 = ((const uint2*)(g_Pb + (size_t)g_adj[i + 5] * 128))[lane];
        uint2 u6 = ((const uint2*)(g_Pb + (size_t)g_adj[i + 6] * 128))[lane];
        uint2 u7 = ((const uint2*)(g_Pb + (size_t)g_adj[i + 7] * 128))[lane];
        acc4(a, u0); acc4(a, u1); acc4(a, u2); acc4(a, u3);
        acc4(a, u4); acc4(a, u5); acc4(a, u6); acc4(a, u7);
    }
    if (i + 4 <= e) {
        uint2 u0 = ((const uint2*)(g_Pb + (size_t)g_adj[i] * 128))[lane];
        uint2 u1 = ((const uint2*)(g_Pb + (size_t)g_adj[i + 1] * 128))[lane];
        uint2 u2 = ((const uint2*)(g_Pb + (size_t)g_adj[i + 2] * 128))[lane];
        uint2 u3 = ((const uint2*)(g_Pb + (size_t)g_adj[i + 3] * 128))[lane];
        acc4(a, u0); acc4(a, u1); acc4(a, u2); acc4(a, u3);
        i += 4;
    }
    for (; i < e; i++) acc4(a, ((const uint2*)(g_Pb + (size_t)g_adj[i] * 128))[lane]);
    int deg = e - s;
    float inv = 1.0f / (float)(deg > 1 ? deg : 1);
    const float4 sf = __ldcs(&((const float4*)(g_Q + (size_t)node * 128))[lane]);
    const float4 bb = ((const float4*)b2)[lane];
    float4 h = f4relu(make_float4(fmaf(a[0], inv, bb.x + sf.x), fmaf(a[1], inv, bb.y + sf.y),
                                  fmaf(a[2], inv, bb.z + sf.z), fmaf(a[3], inv, bb.w + sf.w)));
    float4 wl = ((const float4*)Wl3)[lane];
    float4 wr = ((const float4*)Wr3)[lane];
    float pl = h.x * wl.x + h.y * wl.y + h.z * wl.z + h.w * wl.w;
    float pr = h.x * wr.x + h.y * wr.y + h.z * wr.z + h.w * wr.w;
#pragma unroll
    for (int o = 16; o > 0; o >>= 1) {
        pl += __shfl_down_sync(0xffffffffu, pl, o);
        pr += __shfl_down_sync(0xffffffffu, pr, o);
    }
    if (lane == 0) {
        g_H[node] = pl;
        g_H[NN + node] = pr;
    }
}

__global__ void k_final(const float* __restrict__ b3, float* __restrict__ out) {
    int i = blockIdx.x * blockDim.x + threadIdx.x;
    if (i >= NN) return;
    int s = g_rowptr[i], e = g_rowptr[i + 1];
    float sum = 0.f;
    for (int k = s; k < e; k++) sum += g_H[g_adj[k]];
    int deg = e - s;
    out[i] = sum / (float)(deg > 1 ? deg : 1) + b3[0] + g_H[NN + i];
}

// ---------------- launch ----------------
extern "C" void kernel_launch(void* const* d_in, const int* in_sizes, int n_in, void* d_out,
                              int out_size) {
    const float* x = (const float*)d_in[0];
    const void* ei = d_in[1];
    const float* Wl1 = (const float*)d_in[2];
    const float* bl1 = (const float*)d_in[3];
    const float* Wr1 = (const float*)d_in[4];
    const float* Wl2 = (const float*)d_in[5];
    const float* bl2 = (const float*)d_in[6];
    const float* Wr2 = (const float*)d_in[7];
    const float* Wl3 = (const float*)d_in[8];
    const float* bl3 = (const float*)d_in[9];
    const float* Wr3 = (const float*)d_in[10];
    float* out = (float*)d_out;

    const int SMEM = (2 * 128 * AS_ST + 2 * 32 * BS_ST) * 4;  // 71680 bytes
    static bool attr_set = false;
    if (!attr_set) {
        cudaFuncSetAttribute(k_gemm, cudaFuncAttributeMaxDynamicSharedMemorySize, SMEM);
        attr_set = true;
    }

    int scan_blocks = (NN + 1023) / 1024;  // 98

    // Launch order keeps k_gemm (layer 1) in the ncu capture window (4th launch).
    k_concat<<<(256 * 512 + 255) / 256, 256>>>(Wl1, Wr1, 256, 256);  // 0
    k_detect<<<1, 1024>>>((const int*)ei);                            // 1
    k_zero_cnt<<<(NN + 255) / 256, 256>>>();                          // 2
    dim3 g1(4, (NN + 127) / 128);                                     // x=bn, y=rows: A L2 reuse
    k_gemm<<<g1, 256, SMEM>>>(x, NN, 256, 512);                       // 3 <- profiled
    k_hist<<<(EE + 255) / 256, 256>>>(ei);
    k_scan1<<<scan_blocks, 1024>>>();
    k_scan2<<<1, 1>>>(scan_blocks);
    k_scan3<<<scan_blocks, 1024>>>();
    k_fill<<<(EE + 255) / 256, 256>>>(ei);

    // layer 1 aggregation -> H [N,256]
    k_agg<<<((size_t)NN * 32 + 255) / 256, 256>>>(bl1);

    // layer 2: P2|Q2 = H @ [Wl2|Wr2] (N=256), then agg+relu fused with layer-3 projection
    k_concat<<<(256 * 256 + 255) / 256, 256>>>(Wl2, Wr2, 256, 128);
    dim3 g2(2, (NN + 127) / 128);
    k_gemm<<<g2, 256, SMEM>>>(nullptr, NN, 256, 256);
    k_agg2_fuse<<<((size_t)NN * 32 + 255) / 256, 256>>>(bl2, Wl3, Wr3);

    // layer 3: scalar aggregation
    k_final<<<(NN + 255) / 256, 256>>>(bl3, out);
}

// round 17
// speedup vs baseline: 1.6512x; 1.2868x over previous
#include <cuda_runtime.h>
#include <cuda_fp16.h>
#include <cstdint>
#include <cstddef>

#define NN 100000
#define EE 1600000

// ---------------- scratch (static __device__ arrays; no allocation) ----------------
__device__ __half g_Xb[(size_t)NN * 256];  // x converted to fp16 (GEMM1 A)
__device__ __half g_Hb[(size_t)NN * 256];  // hidden h1 in fp16 (GEMM2 A)
__device__ __half g_Pb[(size_t)NN * 256];  // projected neighbor features, fp16
__device__ float g_Q[(size_t)NN * 256];    // projected self features, fp32
__device__ float g_H[2 * NN];              // layer-3 scalars: p3 = [0..N), q3 = [N..2N)
__device__ __half2 g_Wcat[128 * 512];      // weights, k-pair-interleaved half2 [K/2][N]
__device__ int g_rowptr[NN + 1];
__device__ int g_cursor[NN];
__device__ int g_cnt[NN];
__device__ int g_adj[EE];
__device__ int g_part[128];
__device__ int g_is64;

// ---------------- small helpers ----------------
__device__ __forceinline__ float4 f4relu(float4 a) {
    return make_float4(fmaxf(a.x, 0.f), fmaxf(a.y, 0.f), fmaxf(a.z, 0.f), fmaxf(a.w, 0.f));
}
__device__ __forceinline__ void mma_f16(float* d, const uint32_t* a, const uint32_t* b) {
    asm("mma.sync.aligned.m16n8k16.row.col.f32.f16.f16.f32 "
        "{%0,%1,%2,%3}, {%4,%5,%6,%7}, {%8,%9}, {%0,%1,%2,%3};"
        : "+f"(d[0]), "+f"(d[1]), "+f"(d[2]), "+f"(d[3])
        : "r"(a[0]), "r"(a[1]), "r"(a[2]), "r"(a[3]), "r"(b[0]), "r"(b[1]));
}
__device__ __forceinline__ void cpasync16(void* smem, const void* g, int src_sz) {
    uint32_t s = (uint32_t)__cvta_generic_to_shared(smem);
    asm volatile("cp.async.cg.shared.global [%0], [%1], 16, %2;" ::"r"(s), "l"(g), "r"(src_sz));
}
__device__ __forceinline__ int clampi(int v) {
    return v < 0 ? 0 : (v >= NN ? NN - 1 : v);
}
__device__ __forceinline__ int load_idx(const void* ei, int p) {
    if (g_is64) return clampi((int)((const long long*)ei)[p]);
    return clampi(((const int*)ei)[p]);
}
__device__ __forceinline__ void acc8(float* a, uint4 u) {
    float2 f0 = __half22float2(*(const __half2*)&u.x);
    float2 f1 = __half22float2(*(const __half2*)&u.y);
    float2 f2 = __half22float2(*(const __half2*)&u.z);
    float2 f3 = __half22float2(*(const __half2*)&u.w);
    a[0] += f0.x; a[1] += f0.y; a[2] += f1.x; a[3] += f1.y;
    a[4] += f2.x; a[5] += f2.y; a[6] += f3.x; a[7] += f3.y;
}
__device__ __forceinline__ void acc4(float* a, uint2 u) {
    float2 f0 = __half22float2(*(const __half2*)&u.x);
    float2 f1 = __half22float2(*(const __half2*)&u.y);
    a[0] += f0.x; a[1] += f0.y; a[2] += f1.x; a[3] += f1.y;
}

// ---------------- dtype detection ----------------
__global__ void k_detect(const int* __restrict__ ei32) {
    int t = threadIdx.x;
    int v = ei32[2 * t + 1];
    int all0 = __syncthreads_and(v == 0);
    if (t == 0) g_is64 = all0;
}

// ---------------- x -> fp16 conversion ----------------
__global__ void k_cvt(const float* __restrict__ x) {
    size_t i = (size_t)blockIdx.x * blockDim.x + threadIdx.x;  // one per 8 elems
    if (i >= (size_t)NN * 32) return;
    const float4* src = (const float4*)(x + i * 8);
    float4 v0 = src[0], v1 = src[1];
    uint4 w;
    *(__half2*)&w.x = __floats2half2_rn(v0.x, v0.y);
    *(__half2*)&w.y = __floats2half2_rn(v0.z, v0.w);
    *(__half2*)&w.z = __floats2half2_rn(v1.x, v1.y);
    *(__half2*)&w.w = __floats2half2_rn(v1.z, v1.w);
    ((uint4*)(g_Xb))[i] = w;
}

// ---------------- CSR build ----------------
__global__ void k_zero_cnt() {
    int i = blockIdx.x * blockDim.x + threadIdx.x;
    if (i < NN) g_cnt[i] = 0;
}
__global__ void k_hist(const void* __restrict__ ei) {
    int e = blockIdx.x * blockDim.x + threadIdx.x;
    if (e < EE) atomicAdd(&g_cnt[load_idx(ei, EE + e)], 1);
}
__global__ void k_scan1() {
    __shared__ int wsum[32];
    int t = threadIdx.x;
    int i = blockIdx.x * 1024 + t;
    int v = (i < NN) ? g_cnt[i] : 0;
    int incl = v;
#pragma unroll
    for (int o = 1; o < 32; o <<= 1) {
        int n = __shfl_up_sync(0xffffffffu, incl, o);
        if ((t & 31) >= o) incl += n;
    }
    if ((t & 31) == 31) wsum[t >> 5] = incl;
    __syncthreads();
    if (t < 32) {
        int w = wsum[t];
        int wi = w;
#pragma unroll
        for (int o = 1; o < 32; o <<= 1) {
            int n = __shfl_up_sync(0xffffffffu, wi, o);
            if (t >= o) wi += n;
        }
        wsum[t] = wi - w;
        if (t == 31) g_part[blockIdx.x] = wi;
    }
    __syncthreads();
    if (i < NN) g_rowptr[i] = incl - v + wsum[t >> 5];
}
__global__ void k_scan2(int nb) {
    int acc = 0;
    for (int b = 0; b < nb; b++) {
        int s = g_part[b];
        g_part[b] = acc;
        acc += s;
    }
    g_rowptr[NN] = acc;
}
__global__ void k_scan3() {
    int i = blockIdx.x * 1024 + threadIdx.x;
    if (i < NN) {
        int r = g_rowptr[i] + g_part[blockIdx.x];
        g_rowptr[i] = r;
        g_cursor[i] = r;
    }
}
__global__ void k_fill(const void* __restrict__ ei) {
    int e = blockIdx.x * blockDim.x + threadIdx.x;
    if (e < EE) {
        int dst = load_idx(ei, EE + e);
        int pos = atomicAdd(&g_cursor[dst], 1);
        g_adj[pos] = load_idx(ei, e);
    }
}

// ---------------- weight concat -> k-pair interleaved half2: g_Wcat[kp][n] ----------------
__global__ void k_concat(const float* __restrict__ Wl, const float* __restrict__ Wr, int K, int h) {
    int i = blockIdx.x * blockDim.x + threadIdx.x;
    int N = 2 * h;
    int tot = (K / 2) * N;
    if (i < tot) {
        int kp = i / N;
        int n = i % N;
        float v0 = (n < h) ? Wl[(2 * kp) * h + n] : Wr[(2 * kp) * h + n - h];
        float v1 = (n < h) ? Wl[(2 * kp + 1) * h + n] : Wr[(2 * kp + 1) * h + n - h];
        g_Wcat[i] = __floats2half2_rn(v0, v1);
    }
}

// ---------------- fp16 GEMM: [P|Q][M, Nh each] = A[M,K] @ W[K,N],  N = 2*Nh ----------------
// A fp16 (g_Xb or g_Hb). Block tile 128x128, warp 64x32, k-tile 32 via m16n8k16.
// A smem: [row][kpair] words, stride AS_W. B smem: [kpair][col] words, stride BS_W.
#define AS_W 20    // 16 data words (32 fp16) + 4 pad
#define BS_W 136   // 128 data words + 8 pad

__device__ __forceinline__ void gemm_load_tile(const __half* __restrict__ A, uint32_t* As,
                                               uint32_t* Bs, int bm, int bn, int M, int Kw,
                                               int Nw, int kt, int tid) {
    // A: 128 rows x 16 words, 16B chunks: 512 chunks, 2 per thread
#pragma unroll
    for (int it = 0; it < 2; it++) {
        int c = tid + 256 * it;
        int row = c >> 2, cc = c & 3;
        int gr = bm + row;
        bool val = gr < M;
        const char* src =
            (const char*)A + ((size_t)(val ? gr : 0) * Kw + kt * 16 + cc * 4) * 4;
        cpasync16(&As[row * AS_W + cc * 4], src, val ? 16 : 0);
    }
    // B: 16 kpairs x 128 words, 512 chunks, 2 per thread
    const uint32_t* B = (const uint32_t*)g_Wcat;
#pragma unroll
    for (int it = 0; it < 2; it++) {
        int c = tid + 256 * it;
        int row = c >> 5, cw = c & 31;
        cpasync16(&Bs[row * BS_W + cw * 4], B + (size_t)(kt * 16 + row) * Nw + bn + cw * 4, 16);
    }
    asm volatile("cp.async.commit_group;");
}

__global__ void __launch_bounds__(256, 2) k_gemm(int useX, int M, int K, int N) {
    extern __shared__ uint32_t smem[];
    uint32_t* As0 = smem;                    // 128*20 words
    uint32_t* As1 = smem + 128 * AS_W;
    uint32_t* Bs0 = smem + 2 * 128 * AS_W;   // 16*136 words
    uint32_t* Bs1 = Bs0 + 16 * BS_W;
    const __half* A = useX ? g_Xb : g_Hb;
    int Kw = K >> 1;          // A row words
    int Nw = N;               // Wcat row words (one word per col)

    int tid = threadIdx.x;
    int bm = blockIdx.y * 128, bn = blockIdx.x * 128;
    int warp = tid >> 5, lane = tid & 31;
    int wm = (warp >> 2) * 64, wn = (warp & 3) * 32;
    int grp = lane >> 2, qid = lane & 3;

    int Nh = N >> 1;
    bool isP = (bn < Nh);
    int bncol = isP ? bn : bn - Nh;

    float acc[4][4][4];
#pragma unroll
    for (int i = 0; i < 4; i++)
#pragma unroll
        for (int j = 0; j < 4; j++)
#pragma unroll
            for (int r = 0; r < 4; r++) acc[i][j][r] = 0.f;

    int ktiles = K / 32;
    gemm_load_tile(A, As0, Bs0, bm, bn, M, Kw, Nw, 0, tid);

    for (int kt = 0; kt < ktiles; kt++) {
        if (kt + 1 < ktiles) {
            uint32_t* Asn = ((kt + 1) & 1) ? As1 : As0;
            uint32_t* Bsn = ((kt + 1) & 1) ? Bs1 : Bs0;
            gemm_load_tile(A, Asn, Bsn, bm, bn, M, Kw, Nw, kt + 1, tid);
            asm volatile("cp.async.wait_group 1;");
        } else {
            asm volatile("cp.async.wait_group 0;");
        }
        __syncthreads();

        const uint32_t* Asb = (kt & 1) ? As1 : As0;
        const uint32_t* Bsb = (kt & 1) ? Bs1 : Bs0;
#pragma unroll
        for (int ks = 0; ks < 2; ks++) {        // two 16-deep k-steps per 32-tile
            int kp0 = ks * 8;
            uint32_t af[4][4];
#pragma unroll
            for (int mf = 0; mf < 4; mf++) {
                const uint32_t* ap = &Asb[(wm + mf * 16 + grp) * AS_W + kp0 + qid];
                af[mf][0] = ap[0];               // row grp,   kpair qid
                af[mf][1] = ap[8 * AS_W];        // row grp+8, kpair qid
                af[mf][2] = ap[4];               // row grp,   kpair qid+4
                af[mf][3] = ap[8 * AS_W + 4];    // row grp+8, kpair qid+4
            }
            uint32_t bf[4][2];
#pragma unroll
            for (int nf = 0; nf < 4; nf++) {
                const uint32_t* bp = &Bsb[(kp0 + qid) * BS_W + wn + nf * 8 + grp];
                bf[nf][0] = bp[0];               // kpair qid,   col
                bf[nf][1] = bp[4 * BS_W];        // kpair qid+4, col
            }
#pragma unroll
            for (int mf = 0; mf < 4; mf++)
#pragma unroll
                for (int nf = 0; nf < 4; nf++) mma_f16(acc[mf][nf], af[mf], bf[nf]);
        }
        __syncthreads();
    }

    // epilogue: P half -> fp16, Q half -> fp32
#pragma unroll
    for (int mf = 0; mf < 4; mf++) {
        int r0 = bm + wm + mf * 16 + grp;
#pragma unroll
        for (int nf = 0; nf < 4; nf++) {
            int col = bncol + wn + nf * 8 + qid * 2;
            if (isP) {
                if (r0 < M)
                    *(__half2*)&g_Pb[(size_t)r0 * Nh + col] =
                        __floats2half2_rn(acc[mf][nf][0], acc[mf][nf][1]);
                if (r0 + 8 < M)
                    *(__half2*)&g_Pb[(size_t)(r0 + 8) * Nh + col] =
                        __floats2half2_rn(acc[mf][nf][2], acc[mf][nf][3]);
            } else {
                if (r0 < M)
                    *(float2*)&g_Q[(size_t)r0 * Nh + col] =
                        make_float2(acc[mf][nf][0], acc[mf][nf][1]);
                if (r0 + 8 < M)
                    *(float2*)&g_Q[(size_t)(r0 + 8) * Nh + col] =
                        make_float2(acc[mf][nf][2], acc[mf][nf][3]);
            }
        }
    }
}

// ---------------- layer-1 aggregation: 8-edge unrolled fp16 gather, fp16 H output ----------------
__global__ void k_agg(const float* __restrict__ bias) {
    int node = (int)((blockIdx.x * (unsigned)blockDim.x + threadIdx.x) >> 5);
    if (node >= NN) return;
    int lane = threadIdx.x & 31;
    int s = g_rowptr[node], e = g_rowptr[node + 1];
    float a[8] = {0, 0, 0, 0, 0, 0, 0, 0};
    int i = s;
    for (; i + 8 <= e; i += 8) {
        uint4 u0 = ((const uint4*)(g_Pb + (size_t)g_adj[i] * 256))[lane];
        uint4 u1 = ((const uint4*)(g_Pb + (size_t)g_adj[i + 1] * 256))[lane];
        uint4 u2 = ((const uint4*)(g_Pb + (size_t)g_adj[i + 2] * 256))[lane];
        uint4 u3 = ((const uint4*)(g_Pb + (size_t)g_adj[i + 3] * 256))[lane];
        uint4 u4 = ((const uint4*)(g_Pb + (size_t)g_adj[i + 4] * 256))[lane];
        uint4 u5 = ((const uint4*)(g_Pb + (size_t)g_adj[i + 5] * 256))[lane];
        uint4 u6 = ((const uint4*)(g_Pb + (size_t)g_adj[i + 6] * 256))[lane];
        uint4 u7 = ((const uint4*)(g_Pb + (size_t)g_adj[i + 7] * 256))[lane];
        acc8(a, u0); acc8(a, u1); acc8(a, u2); acc8(a, u3);
        acc8(a, u4); acc8(a, u5); acc8(a, u6); acc8(a, u7);
    }
    if (i + 4 <= e) {
        uint4 u0 = ((const uint4*)(g_Pb + (size_t)g_adj[i] * 256))[lane];
        uint4 u1 = ((const uint4*)(g_Pb + (size_t)g_adj[i + 1] * 256))[lane];
        uint4 u2 = ((const uint4*)(g_Pb + (size_t)g_adj[i + 2] * 256))[lane];
        uint4 u3 = ((const uint4*)(g_Pb + (size_t)g_adj[i + 3] * 256))[lane];
        acc8(a, u0); acc8(a, u1); acc8(a, u2); acc8(a, u3);
        i += 4;
    }
    for (; i < e; i++) acc8(a, ((const uint4*)(g_Pb + (size_t)g_adj[i] * 256))[lane]);
    int deg = e - s;
    float inv = 1.0f / (float)(deg > 1 ? deg : 1);
    int c0 = lane * 8;
    const float4* self = (const float4*)(g_Q + (size_t)node * 256 + c0);
    const float4* bb = (const float4*)(bias + c0);
    float4 s0 = __ldcs(&self[0]), s1 = __ldcs(&self[1]);
    float4 b0 = bb[0], b1 = bb[1];
    float4 o0 = f4relu(make_float4(fmaf(a[0], inv, b0.x + s0.x), fmaf(a[1], inv, b0.y + s0.y),
                                   fmaf(a[2], inv, b0.z + s0.z), fmaf(a[3], inv, b0.w + s0.w)));
    float4 o1 = f4relu(make_float4(fmaf(a[4], inv, b1.x + s1.x), fmaf(a[5], inv, b1.y + s1.y),
                                   fmaf(a[6], inv, b1.z + s1.z), fmaf(a[7], inv, b1.w + s1.w)));
    uint4 w;
    *(__half2*)&w.x = __floats2half2_rn(o0.x, o0.y);
    *(__half2*)&w.y = __floats2half2_rn(o0.z, o0.w);
    *(__half2*)&w.z = __floats2half2_rn(o1.x, o1.y);
    *(__half2*)&w.w = __floats2half2_rn(o1.z, o1.w);
    __stcs((uint4*)(g_Hb + (size_t)node * 256 + c0), w);
}

// ---------------- layer-2 agg fused with layer-3 projection ----------------
__global__ void k_agg2_fuse(const float* __restrict__ b2, const float* __restrict__ Wl3,
                            const float* __restrict__ Wr3) {
    int node = (int)((blockIdx.x * (unsigned)blockDim.x + threadIdx.x) >> 5);
    if (node >= NN) return;
    int lane = threadIdx.x & 31;
    int s = g_rowptr[node], e = g_rowptr[node + 1];
    float a[4] = {0, 0, 0, 0};
    int i = s;
    for (; i + 8 <= e; i += 8) {
        uint2 u0 = ((const uint2*)(g_Pb + (size_t)g_adj[i] * 128))[lane];
        uint2 u1 = ((const uint2*)(g_Pb + (size_t)g_adj[i + 1] * 128))[lane];
        uint2 u2 = ((const uint2*)(g_Pb + (size_t)g_adj[i + 2] * 128))[lane];
        uint2 u3 = ((const uint2*)(g_Pb + (size_t)g_adj[i + 3] * 128))[lane];
        uint2 u4 = ((const uint2*)(g_Pb + (size_t)g_adj[i + 4] * 128))[lane];
        uint2 u5 = ((const uint2*)(g_Pb + (size_t)g_adj[i + 5] * 128))[lane];
        uint2 u6 = ((const uint2*)(g_Pb + (size_t)g_adj[i + 6] * 128))[lane];
        uint2 u7 = ((const uint2*)(g_Pb + (size_t)g_adj[i + 7] * 128))[lane];
        acc4(a, u0); acc4(a, u1); acc4(a, u2); acc4(a, u3);
        acc4(a, u4); acc4(a, u5); acc4(a, u6); acc4(a, u7);
    }
    if (i + 4 <= e) {
        uint2 u0 = ((const uint2*)(g_Pb + (size_t)g_adj[i] * 128))[lane];
        uint2 u1 = ((const uint2*)(g_Pb + (size_t)g_adj[i + 1] * 128))[lane];
        uint2 u2 = ((const uint2*)(g_Pb + (size_t)g_adj[i + 2] * 128))[lane];
        uint2 u3 = ((const uint2*)(g_Pb + (size_t)g_adj[i + 3] * 128))[lane];
        acc4(a, u0); acc4(a, u1); acc4(a, u2); acc4(a, u3);
        i += 4;
    }
    for (; i < e; i++) acc4(a, ((const uint2*)(g_Pb + (size_t)g_adj[i] * 128))[lane]);
    int deg = e - s;
    float inv = 1.0f / (float)(deg > 1 ? deg : 1);
    const float4 sf = __ldcs(&((const float4*)(g_Q + (size_t)node * 128))[lane]);
    const float4 bb = ((const float4*)b2)[lane];
    float4 h = f4relu(make_float4(fmaf(a[0], inv, bb.x + sf.x), fmaf(a[1], inv, bb.y + sf.y),
                                  fmaf(a[2], inv, bb.z + sf.z), fmaf(a[3], inv, bb.w + sf.w)));
    float4 wl = ((const float4*)Wl3)[lane];
    float4 wr = ((const float4*)Wr3)[lane];
    float pl = h.x * wl.x + h.y * wl.y + h.z * wl.z + h.w * wl.w;
    float pr = h.x * wr.x + h.y * wr.y + h.z * wr.z + h.w * wr.w;
#pragma unroll
    for (int o = 16; o > 0; o >>= 1) {
        pl += __shfl_down_sync(0xffffffffu, pl, o);
        pr += __shfl_down_sync(0xffffffffu, pr, o);
    }
    if (lane == 0) {
        g_H[node] = pl;
        g_H[NN + node] = pr;
    }
}

__global__ void k_final(const float* __restrict__ b3, float* __restrict__ out) {
    int i = blockIdx.x * blockDim.x + threadIdx.x;
    if (i >= NN) return;
    int s = g_rowptr[i], e = g_rowptr[i + 1];
    float sum = 0.f;
    for (int k = s; k < e; k++) sum += g_H[g_adj[k]];
    int deg = e - s;
    out[i] = sum / (float)(deg > 1 ? deg : 1) + b3[0] + g_H[NN + i];
}

// ---------------- launch ----------------
extern "C" void kernel_launch(void* const* d_in, const int* in_sizes, int n_in, void* d_out,
                              int out_size) {
    const float* x = (const float*)d_in[0];
    const void* ei = d_in[1];
    const float* Wl1 = (const float*)d_in[2];
    const float* bl1 = (const float*)d_in[3];
    const float* Wr1 = (const float*)d_in[4];
    const float* Wl2 = (const float*)d_in[5];
    const float* bl2 = (const float*)d_in[6];
    const float* Wr2 = (const float*)d_in[7];
    const float* Wl3 = (const float*)d_in[8];
    const float* bl3 = (const float*)d_in[9];
    const float* Wr3 = (const float*)d_in[10];
    float* out = (float*)d_out;

    const int SMEM = (2 * 128 * AS_W + 2 * 16 * BS_W) * 4;  // 37888 bytes
    static bool attr_set = false;
    if (!attr_set) {
        cudaFuncSetAttribute(k_gemm, cudaFuncAttributeMaxDynamicSharedMemorySize, SMEM);
        attr_set = true;
    }

    int scan_blocks = (NN + 1023) / 1024;  // 98

    // Launch order keeps k_gemm (layer 1) in the ncu capture window (4th launch).
    k_concat<<<(128 * 512 + 255) / 256, 256>>>(Wl1, Wr1, 256, 256);   // 0
    k_detect<<<1, 1024>>>((const int*)ei);                             // 1
    k_cvt<<<(NN * 32 + 255) / 256, 256>>>(x);                          // 2
    dim3 g1(4, (NN + 127) / 128);
    k_gemm<<<g1, 256, SMEM>>>(1, NN, 256, 512);                        // 3 <- profiled
    k_zero_cnt<<<(NN + 255) / 256, 256>>>();
    k_hist<<<(EE + 255) / 256, 256>>>(ei);
    k_scan1<<<scan_blocks, 1024>>>();
    k_scan2<<<1, 1>>>(scan_blocks);
    k_scan3<<<scan_blocks, 1024>>>();
    k_fill<<<(EE + 255) / 256, 256>>>(ei);

    // layer 1 aggregation -> Hb [N,256] fp16
    k_agg<<<((size_t)NN * 32 + 255) / 256, 256>>>(bl1);

    // layer 2: P2|Q2 = H @ [Wl2|Wr2] (N=256), then agg+relu fused with layer-3 projection
    k_concat<<<(128 * 256 + 255) / 256, 256>>>(Wl2, Wr2, 256, 128);
    dim3 g2(2, (NN + 127) / 128);
    k_gemm<<<g2, 256, SMEM>>>(0, NN, 256, 256);
    k_agg2_fuse<<<((size_t)NN * 32 + 255) / 256, 256>>>(bl2, Wl3, Wr3);

    // layer 3: scalar aggregation
    k_final<<<(NN + 255) / 256, 256>>>(bl3, out);
}